// round 1
// baseline (speedup 1.0000x reference)
#include <cuda_runtime.h>
#include <math.h>

// Problem constants
#define Bq     64
#define Nq     384
#define NFEAT  16
#define Eq     3
#define NHID   128
#define NOUT   128
#define ST_HID 64
#define ST_OUT 16

// Device scratch (allocation-free rule: __device__ globals)
__device__ float g_supp[Bq * Eq * Nq * NHID];   // 37.7 MB
__device__ float g_h[Bq * Nq * NHID];           // 12.6 MB
__device__ float g_c1[Eq * NFEAT * NHID];       // combined emb+gc1 weight

// ---------------------------------------------------------------------------
// C1[e][f][h] = sum_d emb_w[d][f] * gc1_w[e][d][h]
// (folds h0 = x @ emb_w^T into the first support GEMM)
// ---------------------------------------------------------------------------
__global__ void combine_c1_kernel(const float* __restrict__ emb_w,
                                  const float* __restrict__ gc1_w,
                                  float* __restrict__ c1) {
    int idx = blockIdx.x * blockDim.x + threadIdx.x;
    if (idx >= Eq * NFEAT * NHID) return;
    int h = idx & (NHID - 1);
    int f = (idx >> 7) % NFEAT;
    int e = idx / (NFEAT * NHID);
    float acc = 0.f;
#pragma unroll
    for (int d = 0; d < NFEAT; d++)
        acc += emb_w[d * NFEAT + f] * gc1_w[(e * NFEAT + d) * NHID + h];
    c1[idx] = acc;
}

// ---------------------------------------------------------------------------
// support[b,e,n,h] = sum_d in[b,n,d] * W[e,d,h]
// grid: (N/8, B*E), block: 128 threads (one per h)
// ---------------------------------------------------------------------------
template <int D>
__global__ void support_kernel(const float* __restrict__ in,
                               const float* __restrict__ W,
                               float* __restrict__ supp) {
    __shared__ float inS[8][D];
    const int be = blockIdx.y;
    const int e  = be % Eq;
    const int b  = be / Eq;
    const int n0 = blockIdx.x * 8;
    const int tid = threadIdx.x;

    for (int i = tid; i < 8 * D; i += 128) {
        int r = i / D, d = i % D;
        inS[r][d] = in[((size_t)(b * Nq + n0 + r)) * D + d];
    }
    __syncthreads();

    const float* We = W + (size_t)e * D * NHID;
    float acc[8];
#pragma unroll
    for (int r = 0; r < 8; r++) acc[r] = 0.f;

    const int h = tid;
#pragma unroll 4
    for (int d = 0; d < D; d++) {
        float wv = We[d * NHID + h];
#pragma unroll
        for (int r = 0; r < 8; r++) acc[r] += inS[r][d] * wv;
    }

    float* outp = supp + (((size_t)(b * Eq + e) * Nq + n0) * NHID) + h;
#pragma unroll
    for (int r = 0; r < 8; r++) outp[(size_t)r * NHID] = acc[r];
}

// ---------------------------------------------------------------------------
// out[b,m,h] = sum_e f( sum_n adj[b,e,m,n] * supp[b,e,n,h] ),  f = relu or id
// Tiled GEMM: BM=32 rows, full H=128, BK=32, 256 threads, 4x4 register tile.
// grid: (N/32, B)
// ---------------------------------------------------------------------------
template <bool RELU>
__global__ void agg_kernel(const float* __restrict__ adj,
                           const float* __restrict__ supp,
                           float* __restrict__ out) {
    __shared__ float adjS[32][33];
    __shared__ float supS[32][NHID];

    const int b   = blockIdx.y;
    const int m0  = blockIdx.x * 32;
    const int tid = threadIdx.x;
    const int l   = tid & 31;   // h lane: h = l + 32*j
    const int g   = tid >> 5;   // m group: m = m0 + g*4 + i

    float total[4][4] = {};

    for (int e = 0; e < Eq; e++) {
        float acc[4][4] = {};
        const float* adjBase = adj  + ((size_t)(b * Eq + e) * Nq + m0) * Nq;
        const float* supBase = supp + ((size_t)(b * Eq + e) * Nq) * NHID;

        for (int kt = 0; kt < Nq / 32; kt++) {
            // load adj tile [32m x 32k]
#pragma unroll
            for (int t = 0; t < 4; t++) {
                int idx = tid + t * 256;
                int r = idx >> 5, c = idx & 31;
                adjS[r][c] = adjBase[(size_t)r * Nq + kt * 32 + c];
            }
            // load support tile [32k x 128h]
#pragma unroll
            for (int t = 0; t < 16; t++) {
                int idx = tid + t * 256;
                int r = idx >> 7, c = idx & 127;
                supS[r][c] = supBase[(size_t)(kt * 32 + r) * NHID + c];
            }
            __syncthreads();

#pragma unroll
            for (int kk = 0; kk < 32; kk++) {
                float a0 = adjS[g * 4 + 0][kk];
                float a1 = adjS[g * 4 + 1][kk];
                float a2 = adjS[g * 4 + 2][kk];
                float a3 = adjS[g * 4 + 3][kk];
                float s0 = supS[kk][l];
                float s1 = supS[kk][l + 32];
                float s2 = supS[kk][l + 64];
                float s3 = supS[kk][l + 96];
                acc[0][0] += a0 * s0; acc[0][1] += a0 * s1; acc[0][2] += a0 * s2; acc[0][3] += a0 * s3;
                acc[1][0] += a1 * s0; acc[1][1] += a1 * s1; acc[1][2] += a1 * s2; acc[1][3] += a1 * s3;
                acc[2][0] += a2 * s0; acc[2][1] += a2 * s1; acc[2][2] += a2 * s2; acc[2][3] += a2 * s3;
                acc[3][0] += a3 * s0; acc[3][1] += a3 * s1; acc[3][2] += a3 * s2; acc[3][3] += a3 * s3;
            }
            __syncthreads();
        }

#pragma unroll
        for (int i = 0; i < 4; i++)
#pragma unroll
            for (int j = 0; j < 4; j++)
                total[i][j] += RELU ? fmaxf(acc[i][j], 0.f) : acc[i][j];
    }

#pragma unroll
    for (int i = 0; i < 4; i++) {
        int m = m0 + g * 4 + i;
        float* op = out + ((size_t)(b * Nq + m)) * NHID;
#pragma unroll
        for (int j = 0; j < 4; j++)
            op[l + 32 * j] = total[i][j];
    }
}

// ---------------------------------------------------------------------------
// Head: z1 = tanh(flat @ w1^T + b1); z = z1 @ w2^T + b2;
// s = exp(rescale)*tanh(z[:, :16]); t = z[:, 16:]; out = stack([s,t])
// grid: (B*N/32), block 256
// ---------------------------------------------------------------------------
__global__ void head_kernel(const float* __restrict__ hin,
                            const float* __restrict__ w1,
                            const float* __restrict__ b1,
                            const float* __restrict__ w2,
                            const float* __restrict__ b2,
                            const float* __restrict__ rescale,
                            float* __restrict__ out) {
    __shared__ float w1T[NOUT][ST_HID];     // [d][hid], 32 KB
    __shared__ float z1S[32][ST_HID + 1];   // 8.3 KB
    __shared__ float zS[32][2 * ST_OUT + 1];// 4.2 KB

    const int tid  = threadIdx.x;
    const int row0 = blockIdx.x * 32;

    for (int i = tid; i < ST_HID * NOUT; i += 256) {
        int hid = i >> 7, d = i & 127;
        w1T[d][hid] = w1[i];
    }
    __syncthreads();

    // stage 1: z1[row][hid], 32*64 = 2048 dots of length 128
    for (int p = tid; p < 32 * ST_HID; p += 256) {
        int row = p >> 6, hid = p & 63;
        const float* fr = hin + ((size_t)(row0 + row)) * NOUT;
        float acc = b1[hid];
#pragma unroll 8
        for (int d = 0; d < NOUT; d++)
            acc += fr[d] * w1T[d][hid];
        z1S[row][hid] = tanhf(acc);
    }
    __syncthreads();

    // stage 2: z[row][j], 32*32 dots of length 64
    for (int p = tid; p < 32 * (2 * ST_OUT); p += 256) {
        int row = p >> 5, j = p & 31;
        float acc = b2[j];
#pragma unroll 8
        for (int k = 0; k < ST_HID; k++)
            acc += z1S[row][k] * w2[j * ST_HID + k];
        zS[row][j] = acc;
    }
    __syncthreads();

    // stage 3: outputs
    const float ew = expf(rescale[0]);
    for (int p = tid; p < 32 * ST_OUT; p += 256) {
        int row = p >> 4, j = p & 15;
        int grow = row0 + row;
        out[(size_t)grow * ST_OUT + j] = ew * tanhf(zS[row][j]);
        out[(size_t)Bq * Nq * ST_OUT + (size_t)grow * ST_OUT + j] = zS[row][j + ST_OUT];
    }
}

// ---------------------------------------------------------------------------
extern "C" void kernel_launch(void* const* d_in, const int* in_sizes, int n_in,
                              void* d_out, int out_size) {
    const float* x       = (const float*)d_in[0];
    const float* adj     = (const float*)d_in[1];
    const float* emb_w   = (const float*)d_in[2];
    const float* gc1_w   = (const float*)d_in[3];
    const float* gc2_w   = (const float*)d_in[4];
    const float* gc3_w   = (const float*)d_in[5];
    const float* st_w1   = (const float*)d_in[6];
    const float* st_b1   = (const float*)d_in[7];
    const float* st_w2   = (const float*)d_in[8];
    const float* st_b2   = (const float*)d_in[9];
    const float* rescale = (const float*)d_in[10];
    float* out = (float*)d_out;

    float *supp, *h, *c1;
    cudaGetSymbolAddress((void**)&supp, g_supp);
    cudaGetSymbolAddress((void**)&h,    g_h);
    cudaGetSymbolAddress((void**)&c1,   g_c1);

    dim3 sgrid(Nq / 8, Bq * Eq);
    dim3 agrid(Nq / 32, Bq);

    // Layer 1 (embedding folded into C1)
    combine_c1_kernel<<<(Eq * NFEAT * NHID + 255) / 256, 256>>>(emb_w, gc1_w, c1);
    support_kernel<NFEAT><<<sgrid, 128>>>(x, c1, supp);
    agg_kernel<true><<<agrid, 256>>>(adj, supp, h);

    // Layer 2
    support_kernel<NHID><<<sgrid, 128>>>(h, gc2_w, supp);
    agg_kernel<true><<<agrid, 256>>>(adj, supp, h);

    // Layer 3 (no relu)
    support_kernel<NHID><<<sgrid, 128>>>(h, gc3_w, supp);
    agg_kernel<false><<<agrid, 256>>>(adj, supp, h);

    // Head
    head_kernel<<<(Bq * Nq) / 32, 256>>>(h, st_w1, st_b1, st_w2, st_b2, rescale, out);
}

// round 2
// speedup vs baseline: 1.0383x; 1.0383x over previous
#include <cuda_runtime.h>
#include <math.h>

#define Bq     64
#define Nq     384
#define NFEAT  16
#define Eq     3
#define NHID   128
#define ST_HID 64
#define ST_OUT 16
#define MFLAT  (Bq * Nq)

typedef unsigned long long ull;

__device__ __forceinline__ ull pk(float x, float y) {
    ull r; asm("mov.b64 %0,{%1,%2};" : "=l"(r) : "f"(x), "f"(y)); return r;
}
__device__ __forceinline__ void upk(ull v, float& x, float& y) {
    asm("mov.b64 {%0,%1},%2;" : "=f"(x), "=f"(y) : "l"(v));
}
__device__ __forceinline__ void fma2(ull& d, ull a, ull b) {
    asm("fma.rn.f32x2 %0,%1,%2,%0;" : "+l"(d) : "l"(a), "l"(b));
}

// Device scratch
__device__ float g_supp[Bq * Eq * Nq * NHID];  // 37.7 MB
__device__ float g_oe[Bq * Eq * Nq * NHID];    // 37.7 MB (per-relation outputs)
__device__ float g_c1[Eq * NFEAT * NHID];

// ---------------------------------------------------------------------------
// C1[e][f][h] = sum_d emb_w[d][f] * gc1_w[e][d][h]
// ---------------------------------------------------------------------------
__global__ void combine_c1_kernel(const float* __restrict__ emb_w,
                                  const float* __restrict__ gc1_w,
                                  float* __restrict__ c1) {
    int idx = blockIdx.x * blockDim.x + threadIdx.x;
    if (idx >= Eq * NFEAT * NHID) return;
    int h = idx & (NHID - 1);
    int f = (idx >> 7) % NFEAT;
    int e = idx / (NFEAT * NHID);
    float acc = 0.f;
#pragma unroll
    for (int d = 0; d < NFEAT; d++)
        acc += emb_w[d * NFEAT + f] * gc1_w[(e * NFEAT + d) * NHID + h];
    c1[idx] = acc;
}

// ---------------------------------------------------------------------------
// Per-relation aggregation GEMM:
//   oe[b,e,m,h] = act( sum_n adj[b,e,m,n] * supp[b,e,n,h] )
// BM=64, BN=128, BK=32, 256 threads, 4m x 8h per thread, fma.rn.f32x2.
// grid: (Nq/64, Bq*Eq)
// ---------------------------------------------------------------------------
template <bool RELU>
__global__ __launch_bounds__(256, 2)
void agg_e_kernel(const float* __restrict__ adj,
                  const float* __restrict__ supp,
                  float* __restrict__ oe) {
    __shared__ float2 aS[64][33];     // adj duplicated {v,v}, padded
    __shared__ float  sS[32][NHID];   // support tile

    const int be  = blockIdx.y;
    const int m0  = blockIdx.x * 64;
    const int tid = threadIdx.x;
    const int hg  = tid & 15;   // h0 = hg*8
    const int mg  = tid >> 4;   // m  = m0 + mg*4 + i

    const float* adjBase = adj  + ((size_t)be * Nq + m0) * Nq;
    const float* supBase = supp + (size_t)be * Nq * NHID;

    ull acc[4][4];
#pragma unroll
    for (int i = 0; i < 4; i++)
#pragma unroll
        for (int j = 0; j < 4; j++) acc[i][j] = pk(0.f, 0.f);

    for (int kt = 0; kt < Nq / 32; kt++) {
        // fill adj tile (duplicated pairs)
#pragma unroll
        for (int t = 0; t < 2; t++) {
            int idx = tid + t * 256;           // [0,512)
            int m = idx >> 3, kq = idx & 7;
            float4 v = *(const float4*)(adjBase + (size_t)m * Nq + kt * 32 + kq * 4);
            aS[m][kq * 4 + 0] = make_float2(v.x, v.x);
            aS[m][kq * 4 + 1] = make_float2(v.y, v.y);
            aS[m][kq * 4 + 2] = make_float2(v.z, v.z);
            aS[m][kq * 4 + 3] = make_float2(v.w, v.w);
        }
        // fill support tile
#pragma unroll
        for (int t = 0; t < 4; t++) {
            int idx = tid + t * 256;           // [0,1024)
            int r = idx >> 5, c = idx & 31;
            *(float4*)&sS[r][c * 4] =
                *(const float4*)(supBase + (size_t)(kt * 32 + r) * NHID + c * 4);
        }
        __syncthreads();

#pragma unroll 8
        for (int kk = 0; kk < 32; kk++) {
            ull a[4];
#pragma unroll
            for (int i = 0; i < 4; i++)
                a[i] = *(const ull*)&aS[mg * 4 + i][kk];
            float4 v0 = *(const float4*)&sS[kk][hg * 8];
            float4 v1 = *(const float4*)&sS[kk][hg * 8 + 4];
            ull s[4] = { pk(v0.x, v0.y), pk(v0.z, v0.w),
                         pk(v1.x, v1.y), pk(v1.z, v1.w) };
#pragma unroll
            for (int i = 0; i < 4; i++)
#pragma unroll
                for (int j = 0; j < 4; j++)
                    fma2(acc[i][j], a[i], s[j]);
        }
        __syncthreads();
    }

#pragma unroll
    for (int i = 0; i < 4; i++) {
        float o[8];
#pragma unroll
        for (int j = 0; j < 4; j++) upk(acc[i][j], o[2 * j], o[2 * j + 1]);
        if (RELU) {
#pragma unroll
            for (int j = 0; j < 8; j++) o[j] = fmaxf(o[j], 0.f);
        }
        float* op = oe + ((size_t)be * Nq + m0 + mg * 4 + i) * NHID + hg * 8;
        *(float4*)op       = make_float4(o[0], o[1], o[2], o[3]);
        *(float4*)(op + 4) = make_float4(o[4], o[5], o[6], o[7]);
    }
}

// ---------------------------------------------------------------------------
// Support GEMM: supp[b,e,n,h] = in_row[m,:] @ W[e]
// NE==3: in_row = sum over relations of oe rows (sum fused into load).
// Same tile scheme as agg. grid: (MFLAT/64, Eq)
// ---------------------------------------------------------------------------
template <int K, int NE>
__global__ __launch_bounds__(256, 2)
void support_gemm(const float* __restrict__ in,
                  const float* __restrict__ W,
                  float* __restrict__ supp) {
    constexpr int BK = (K >= 32) ? 32 : K;
    __shared__ float2 aS[64][BK + 1];
    __shared__ float  wS[BK][NHID];

    const int e   = blockIdx.y;
    const int m0  = blockIdx.x * 64;
    const int b   = m0 / Nq;
    const int n0  = m0 % Nq;
    const int tid = threadIdx.x;
    const int hg  = tid & 15;
    const int mg  = tid >> 4;

    const float* We = W + (size_t)e * K * NHID;
    const size_t eStride = (size_t)Nq * NHID;
    const float* inBase = (NE == 1)
        ? in + (size_t)m0 * K
        : in + ((size_t)(b * Eq) * Nq + n0) * NHID;

    ull acc[4][4];
#pragma unroll
    for (int i = 0; i < 4; i++)
#pragma unroll
        for (int j = 0; j < 4; j++) acc[i][j] = pk(0.f, 0.f);

#pragma unroll
    for (int kt = 0; kt < K / BK; kt++) {
        // fill input tile (summing relations if NE==3)
        constexpr int NIT = (64 * BK / 4) / 256;   // 1 (BK=16) or 2 (BK=32)
#pragma unroll
        for (int t = 0; t < NIT; t++) {
            int idx = tid + t * 256;
            int m = idx / (BK / 4), kq = idx % (BK / 4);
            const float* rp = (NE == 1)
                ? inBase + (size_t)m * K + kt * BK + kq * 4
                : inBase + (size_t)m * NHID + kt * BK + kq * 4;
            float4 v = *(const float4*)rp;
            if (NE == 3) {
                float4 v1 = *(const float4*)(rp + eStride);
                float4 v2 = *(const float4*)(rp + 2 * eStride);
                v.x += v1.x + v2.x; v.y += v1.y + v2.y;
                v.z += v1.z + v2.z; v.w += v1.w + v2.w;
            }
            aS[m][kq * 4 + 0] = make_float2(v.x, v.x);
            aS[m][kq * 4 + 1] = make_float2(v.y, v.y);
            aS[m][kq * 4 + 2] = make_float2(v.z, v.z);
            aS[m][kq * 4 + 3] = make_float2(v.w, v.w);
        }
        // fill weight tile
#pragma unroll
        for (int t = 0; t < (BK * NHID / 4) / 256; t++) {
            int idx = tid + t * 256;
            int r = idx >> 5, c = idx & 31;
            *(float4*)&wS[r][c * 4] =
                *(const float4*)(We + (size_t)(kt * BK + r) * NHID + c * 4);
        }
        __syncthreads();

#pragma unroll 8
        for (int kk = 0; kk < BK; kk++) {
            ull a[4];
#pragma unroll
            for (int i = 0; i < 4; i++)
                a[i] = *(const ull*)&aS[mg * 4 + i][kk];
            float4 v0 = *(const float4*)&wS[kk][hg * 8];
            float4 v1 = *(const float4*)&wS[kk][hg * 8 + 4];
            ull s[4] = { pk(v0.x, v0.y), pk(v0.z, v0.w),
                         pk(v1.x, v1.y), pk(v1.z, v1.w) };
#pragma unroll
            for (int i = 0; i < 4; i++)
#pragma unroll
                for (int j = 0; j < 4; j++)
                    fma2(acc[i][j], a[i], s[j]);
        }
        __syncthreads();
    }

#pragma unroll
    for (int i = 0; i < 4; i++) {
        float o[8];
#pragma unroll
        for (int j = 0; j < 4; j++) upk(acc[i][j], o[2 * j], o[2 * j + 1]);
        float* op = supp + (((size_t)(b * Eq + e) * Nq) + n0 + mg * 4 + i) * NHID + hg * 8;
        *(float4*)op       = make_float4(o[0], o[1], o[2], o[3]);
        *(float4*)(op + 4) = make_float4(o[4], o[5], o[6], o[7]);
    }
}

// ---------------------------------------------------------------------------
// Head: rows summed over relations, then
// z1 = tanh(row @ w1^T + b1); z = z1 @ w2^T + b2;
// out[0] = exp(rescale)*tanh(z[:, :16]); out[1] = z[:, 16:]
// 16 rows / block, 256 threads. grid: MFLAT/16
// ---------------------------------------------------------------------------
__global__ __launch_bounds__(256)
void head_kernel(const float* __restrict__ oe,
                 const float* __restrict__ w1,
                 const float* __restrict__ b1,
                 const float* __restrict__ w2,
                 const float* __restrict__ b2,
                 const float* __restrict__ rescale,
                 float* __restrict__ out) {
    __shared__ float w1T[NHID][68];      // [d][hid], padded for f4 reads
    __shared__ float hS[16][NHID];
    __shared__ float z1S[16][68];

    const int tid  = threadIdx.x;
    const int row0 = blockIdx.x * 16;
    const int b    = row0 / Nq;
    const int n0   = row0 % Nq;

    for (int i = tid; i < ST_HID * NHID; i += 256) {
        int hid = i >> 7, d = i & 127;
        w1T[d][hid] = w1[i];
    }

    const float* base = oe + ((size_t)(b * Eq) * Nq + n0) * NHID;
    const size_t eS = (size_t)Nq * NHID;
#pragma unroll
    for (int t = 0; t < 2; t++) {
        int idx = tid + t * 256;           // [0,512)
        int r = idx >> 5, c = idx & 31;
        float4 v0 = *(const float4*)(base + (size_t)r * NHID + c * 4);
        float4 v1 = *(const float4*)(base + eS + (size_t)r * NHID + c * 4);
        float4 v2 = *(const float4*)(base + 2 * eS + (size_t)r * NHID + c * 4);
        float4 s = make_float4(v0.x + v1.x + v2.x, v0.y + v1.y + v2.y,
                               v0.z + v1.z + v2.z, v0.w + v1.w + v2.w);
        *(float4*)&hS[r][c * 4] = s;
    }
    __syncthreads();

    // stage 1: z1[row][hid] over 4 hid per thread
    {
        int row = tid >> 4, hg = tid & 15;
        float a0 = b1[hg * 4 + 0], a1 = b1[hg * 4 + 1];
        float a2 = b1[hg * 4 + 2], a3 = b1[hg * 4 + 3];
#pragma unroll 8
        for (int d = 0; d < NHID; d++) {
            float h = hS[row][d];
            float4 w = *(const float4*)&w1T[d][hg * 4];
            a0 = fmaf(h, w.x, a0); a1 = fmaf(h, w.y, a1);
            a2 = fmaf(h, w.z, a2); a3 = fmaf(h, w.w, a3);
        }
        z1S[row][hg * 4 + 0] = tanhf(a0);
        z1S[row][hg * 4 + 1] = tanhf(a1);
        z1S[row][hg * 4 + 2] = tanhf(a2);
        z1S[row][hg * 4 + 3] = tanhf(a3);
    }
    __syncthreads();

    // stage 2+3: z[row][j], write outputs directly
    const float ew = expf(rescale[0]);
    for (int p = tid; p < 16 * 32; p += 256) {
        int row = p >> 5, j = p & 31;
        float acc = b2[j];
#pragma unroll 8
        for (int k = 0; k < ST_HID; k++)
            acc += z1S[row][k] * w2[j * ST_HID + k];
        int grow = row0 + row;
        if (j < ST_OUT)
            out[(size_t)grow * ST_OUT + j] = ew * tanhf(acc);
        else
            out[(size_t)MFLAT * ST_OUT + (size_t)grow * ST_OUT + (j - ST_OUT)] = acc;
    }
}

// ---------------------------------------------------------------------------
extern "C" void kernel_launch(void* const* d_in, const int* in_sizes, int n_in,
                              void* d_out, int out_size) {
    const float* x       = (const float*)d_in[0];
    const float* adj     = (const float*)d_in[1];
    const float* emb_w   = (const float*)d_in[2];
    const float* gc1_w   = (const float*)d_in[3];
    const float* gc2_w   = (const float*)d_in[4];
    const float* gc3_w   = (const float*)d_in[5];
    const float* st_w1   = (const float*)d_in[6];
    const float* st_b1   = (const float*)d_in[7];
    const float* st_w2   = (const float*)d_in[8];
    const float* st_b2   = (const float*)d_in[9];
    const float* rescale = (const float*)d_in[10];
    float* out = (float*)d_out;

    float *supp, *oe, *c1;
    cudaGetSymbolAddress((void**)&supp, g_supp);
    cudaGetSymbolAddress((void**)&oe,   g_oe);
    cudaGetSymbolAddress((void**)&c1,   g_c1);

    dim3 sgrid(MFLAT / 64, Eq);          // (384, 3)
    dim3 agrid(Nq / 64, Bq * Eq);        // (6, 192)

    combine_c1_kernel<<<(Eq * NFEAT * NHID + 255) / 256, 256>>>(emb_w, gc1_w, c1);

    // Layer 1 (embedding folded into C1)
    support_gemm<NFEAT, 1><<<sgrid, 256>>>(x, c1, supp);
    agg_e_kernel<true><<<agrid, 256>>>(adj, supp, oe);

    // Layer 2
    support_gemm<NHID, 3><<<sgrid, 256>>>(oe, gc2_w, supp);
    agg_e_kernel<true><<<agrid, 256>>>(adj, supp, oe);

    // Layer 3 (no relu)
    support_gemm<NHID, 3><<<sgrid, 256>>>(oe, gc3_w, supp);
    agg_e_kernel<false><<<agrid, 256>>>(adj, supp, oe);

    // Head (sums relations on load)
    head_kernel<<<MFLAT / 16, 256>>>(oe, st_w1, st_b1, st_w2, st_b2, rescale, out);
}